// round 3
// baseline (speedup 1.0000x reference)
#include <cuda_runtime.h>
#include <cstdint>
#include <math.h>

// Fixed shapes: inputs (32,64,64,64) f32, weight (512,64) f32
#define N_TOK    131072
#define KCODES   512
#define DDIM     64
#define TILE_M   128
#define NTHREADS 256
#define NCTAS    152                 // one persistent CTA per SM
#define NTILES_T (N_TOK / TILE_M)    // 1024
#define OUT_ELEMS (N_TOK * DDIM)

// ---- device scratch ----
__device__ int    g_counts[KCODES];
__device__ float  g_sw[KCODES];
__device__ double g_partial[NCTAS];

// ---- shared memory layout (32-bit word offsets) ----
// Wp: fp16x2 packed weights, [dpair 0..31][code 0..511] stride 520 (520%32==8 -> conflict-free B frags)
#define WS_WORDS  (32 * 520)                  // 16640
#define XS0_OFF   (WS_WORDS)                  // 16640
#define XS_WORDS  (TILE_M * 65)               // 8320  fp32 X, [token][d] stride 65
#define XS1_OFF   (XS0_OFF + XS_WORDS)        // 24960
#define SW_OFF    (XS1_OFF + XS_WORDS)        // 33280
#define CANDI_OFF (SW_OFF + KCODES)           // 33792  (8 candidate indices per token)
#define IDX_OFF   (CANDI_OFF + 8 * TILE_M)    // 34816
#define RED_OFF   (IDX_OFF + TILE_M)          // 34944 (byte 139776, 8-aligned)
#define SMEM_WORDS (RED_OFF + 2 * NTHREADS)   // 35456
#define SMEM_BYTES (SMEM_WORDS * 4)           // 141824

__device__ __forceinline__ bool better(float v, int i, float u, int j) {
    return (v < u) || (v == u && i < j);
}

// Branchless streaming top-2. VALID ONLY for strictly ascending candidate
// indices: strict < then keeps lowest-index on ties == (score,index) total order.
__device__ __forceinline__ void top2_upd(float& v1, int& i1, float& v2, int& i2, float s, int c) {
    bool b1 = s < v1;
    bool b2 = s < v2;
    float nv2 = b1 ? v1 : (b2 ? s : v2);
    int   ni2 = b1 ? i1 : (b2 ? c : i2);
    v2 = nv2; i2 = ni2;
    v1 = b1 ? s : v1;
    i1 = b1 ? c : i1;
}

__device__ __forceinline__ void mma_f16(float& c0, float& c1, float& c2, float& c3,
                                        uint32_t a0, uint32_t a1, uint32_t a2, uint32_t a3,
                                        uint32_t b0, uint32_t b1) {
    asm volatile(
        "mma.sync.aligned.m16n8k16.row.col.f32.f16.f16.f32 "
        "{%0,%1,%2,%3}, {%4,%5,%6,%7}, {%8,%9}, {%0,%1,%2,%3};\n"
        : "+f"(c0), "+f"(c1), "+f"(c2), "+f"(c3)
        : "r"(a0), "r"(a1), "r"(a2), "r"(a3), "r"(b0), "r"(b1));
}

// pack two f32 -> f16x2, lo in low half (first PTX source is the HIGH half)
__device__ __forceinline__ uint32_t pack_f16x2(float lo, float hi) {
    uint32_t u;
    asm("cvt.rn.f16x2.f32 %0, %1, %2;" : "=r"(u) : "f"(hi), "f"(lo));
    return u;
}

__device__ __forceinline__ void cp_async4(uint32_t dst_smem, const float* src) {
    asm volatile("cp.async.ca.shared.global [%0], [%1], 4;\n"
                 :: "r"(dst_smem), "l"(src) : "memory");
}

// K0: zero counts + exact ||w_k||^2 (warp per 4 rows)
__global__ void vq_prep(const float* __restrict__ w) {
    int tid  = threadIdx.x;
    int gtid = blockIdx.x * blockDim.x + tid;
    if (gtid < KCODES) g_counts[gtid] = 0;
    int gw   = blockIdx.x * 8 + (tid >> 5);
    int lane = tid & 31;
#pragma unroll
    for (int r = 0; r < 4; r++) {
        int row = gw * 4 + r;
        float2 v = ((const float2*)(w + row * DDIM))[lane];
        float s = fmaf(v.x, v.x, v.y * v.y);
#pragma unroll
        for (int m = 16; m > 0; m >>= 1) s += __shfl_xor_sync(0xffffffffu, s, m);
        if (lane == 0) g_sw[row] = s;
    }
}

// K1: persistent. fp16 MMA scores -> per-lane top2 -> 8-cand exact rescore -> fused epilogue.
__global__ void __launch_bounds__(NTHREADS, 1)
vq_main(const float* __restrict__ x, const float* __restrict__ w, float* __restrict__ out) {
    extern __shared__ uint32_t sm[];
    uint32_t* Wp    = sm;
    float*    sws   = (float*)(sm + SW_OFF);
    int*      candI = (int*)  (sm + CANDI_OFF);
    int*      idxs  = (int*)  (sm + IDX_OFF);
    double*   red   = (double*)(sm + RED_OFF);

    const int tid = threadIdx.x;
    const int bid = blockIdx.x;
    const int lane = tid & 31, warp = tid >> 5;
    const int g = lane >> 2, tg = lane & 3;
    const int rowTok = warp * 16;

    // ---- stage W once as fp16x2: word = (w[c][2dp], w[c][2dp+1]) at Wp[dp*520 + c] ----
    for (int q = tid; q < KCODES * 32; q += NTHREADS) {
        int c = q >> 5, dp = q & 31;
        float2 wv = *(const float2*)(w + c * DDIM + dp * 2);
        Wp[dp * 520 + c] = pack_f16x2(wv.x, wv.y);
    }
    for (int q = tid; q < KCODES; q += NTHREADS) sws[q] = g_sw[q];

    const int ntiles = (NTILES_T - bid + NCTAS - 1) / NCTAS;

    // ---- prefetch tile 0 ----
    {
        int T0 = bid * TILE_M;
        const float* xb = x + (size_t)(T0 >> 12) * 262144 + (T0 & 4095);
        uint32_t xs = (uint32_t)__cvta_generic_to_shared(sm + XS0_OFF);
#pragma unroll
        for (int it = 0; it < 32; it++) {
            int q = it * NTHREADS + tid;
            int d = q >> 7, tl = q & 127;
            cp_async4(xs + (uint32_t)(tl * 65 + d) * 4u, xb + d * 4096 + tl);
        }
        asm volatile("cp.async.commit_group;\n" ::: "memory");
    }

    double accD = 0.0;

    for (int j = 0; j < ntiles; j++) {
        const int T0 = (bid + j * NCTAS) * TILE_M;
        float* Xs = (float*)(sm + ((j & 1) ? XS1_OFF : XS0_OFF));

        asm volatile("cp.async.wait_group 0;\n" ::: "memory");
        __syncthreads();

        if (j + 1 < ntiles) {
            int nT0 = (bid + (j + 1) * NCTAS) * TILE_M;
            const float* xb = x + (size_t)(nT0 >> 12) * 262144 + (nT0 & 4095);
            uint32_t xsn = (uint32_t)__cvta_generic_to_shared(
                sm + (((j + 1) & 1) ? XS1_OFF : XS0_OFF));
#pragma unroll
            for (int it = 0; it < 32; it++) {
                int q = it * NTHREADS + tid;
                int d = q >> 7, tl = q & 127;
                cp_async4(xsn + (uint32_t)(tl * 65 + d) * 4u, xb + d * 4096 + tl);
            }
            asm volatile("cp.async.commit_group;\n" ::: "memory");
        }

        // ---- A fragments (fp16x2) for 4 k-blocks of 16 ----
        uint32_t a[4][4];
#pragma unroll
        for (int ks = 0; ks < 4; ks++) {
            const float* xr  = Xs + (rowTok + g) * 65 + ks * 16;
            const float* xr8 = Xs + (rowTok + g + 8) * 65 + ks * 16;
            a[ks][0] = pack_f16x2(xr [tg * 2],     xr [tg * 2 + 1]);
            a[ks][1] = pack_f16x2(xr8[tg * 2],     xr8[tg * 2 + 1]);
            a[ks][2] = pack_f16x2(xr [tg * 2 + 8], xr [tg * 2 + 9]);
            a[ks][3] = pack_f16x2(xr8[tg * 2 + 8], xr8[tg * 2 + 9]);
        }

        float v1a = 3.4e38f, v2a = 3.4e38f, v1b = 3.4e38f, v2b = 3.4e38f;
        int   i1a = 0, i2a = 0, i1b = 0, i2b = 0;

        for (int nc = 0; nc < 8; nc++) {            // 64 codes per chunk
            float acc[8][4];
#pragma unroll
            for (int nt = 0; nt < 8; nt++) { acc[nt][0]=0.f; acc[nt][1]=0.f; acc[nt][2]=0.f; acc[nt][3]=0.f; }
            const int c0 = nc * 64;
#pragma unroll
            for (int ks = 0; ks < 4; ks++) {
                const uint32_t* wr = Wp + (ks * 8 + tg) * 520 + c0 + g;
#pragma unroll
                for (int nt = 0; nt < 8; nt++) {
                    uint32_t b0 = wr[nt * 8];
                    uint32_t b1 = wr[nt * 8 + 2080];    // +4 dpairs (4*520)
                    mma_f16(acc[nt][0], acc[nt][1], acc[nt][2], acc[nt][3],
                            a[ks][0], a[ks][1], a[ks][2], a[ks][3], b0, b1);
                }
            }
            // score = sw - 2*dot ; candidates strictly ascending per thread
#pragma unroll
            for (int nt = 0; nt < 8; nt++) {
                int c = c0 + nt * 8 + tg * 2;
                float2 swp = *(const float2*)&sws[c];
                float s0 = fmaf(-2.f, acc[nt][0], swp.x);   // row g,   col c
                float s1 = fmaf(-2.f, acc[nt][1], swp.y);   // row g,   col c+1
                float s2 = fmaf(-2.f, acc[nt][2], swp.x);   // row g+8, col c
                float s3 = fmaf(-2.f, acc[nt][3], swp.y);   // row g+8, col c+1
                top2_upd(v1a, i1a, v2a, i2a, s0, c);
                top2_upd(v1a, i1a, v2a, i2a, s1, c + 1);
                top2_upd(v1b, i1b, v2b, i2b, s2, c);
                top2_upd(v1b, i1b, v2b, i2b, s3, c + 1);
            }
        }

        // ---- every lane writes its top-2 indices: 8 candidates per token ----
        {
            int ta = rowTok + g, tb = rowTok + g + 8;
            candI[ta * 8 + tg * 2]     = i1a;
            candI[ta * 8 + tg * 2 + 1] = i2a;
            candI[tb * 8 + tg * 2]     = i1b;
            candI[tb * 8 + tg * 2 + 1] = i2b;
        }
        __syncthreads();

        // ---- exact fp32 rescore of all 8 candidates per token (2 threads/token) ----
        {
            int t = tid >> 1, half = tid & 1;
            float sx = 0.f;
#pragma unroll
            for (int d = 0; d < DDIM; d++) {
                float xv = Xs[t * 65 + d];
                sx = fmaf(xv, xv, sx);
            }
            float bestV = 3.4e38f; int bestI = 0x7fffffff;
#pragma unroll
            for (int q = 0; q < 4; q++) {
                int c = candI[t * 8 + half * 4 + q];
                const float4* wr4 = (const float4*)(w + c * DDIM);
                float dot = 0.f;
#pragma unroll
                for (int i = 0; i < 16; i++) {
                    float4 wv = wr4[i];
                    dot = fmaf(Xs[t * 65 + i * 4 + 0], wv.x, dot);
                    dot = fmaf(Xs[t * 65 + i * 4 + 1], wv.y, dot);
                    dot = fmaf(Xs[t * 65 + i * 4 + 2], wv.z, dot);
                    dot = fmaf(Xs[t * 65 + i * 4 + 3], wv.w, dot);
                }
                float dist = __fadd_rn(__fadd_rn(sx, -__fmul_rn(2.f, dot)), sws[c]);
                if (better(dist, c, bestV, bestI)) { bestV = dist; bestI = c; }
            }
            float dOth = __shfl_xor_sync(0xffffffffu, bestV, 1);
            int   cOth = __shfl_xor_sync(0xffffffffu, bestI, 1);
            if (half == 0) {
                int pick = better(dOth, cOth, bestV, bestI) ? cOth : bestI;
                idxs[t] = pick;
                atomicAdd(&g_counts[pick], 1);
            }
        }
        __syncthreads();

        // ---- fused epilogue: out from smem x + gathered w; accumulate mse ----
        {
            size_t base4 = (size_t)T0 * 16;
            float4* out4 = (float4*)out + base4;
#pragma unroll
            for (int it = 0; it < 8; it++) {
                int q4 = it * NTHREADS + tid;
                int tl = q4 >> 4, dq = q4 & 15;
                int c  = idxs[tl];
                float4 wv = ((const float4*)(w + c * DDIM))[dq];
                float x0 = Xs[tl * 65 + dq * 4 + 0];
                float x1 = Xs[tl * 65 + dq * 4 + 1];
                float x2 = Xs[tl * 65 + dq * 4 + 2];
                float x3 = Xs[tl * 65 + dq * 4 + 3];
                float d0 = wv.x - x0, d1 = wv.y - x1, d2 = wv.z - x2, d3 = wv.w - x3;
                float4 r;
                r.x = x0 + d0; r.y = x1 + d1; r.z = x2 + d2; r.w = x3 + d3;
                out4[q4] = r;
                accD += (double)d0 * d0 + (double)d1 * d1 + (double)d2 * d2 + (double)d3 * d3;
            }
        }
    }

    red[tid] = accD;
    __syncthreads();
    for (int s = NTHREADS / 2; s > 0; s >>= 1) {
        if (tid < s) red[tid] += red[tid + s];
        __syncthreads();
    }
    if (tid == 0) g_partial[bid] = red[0];
}

// K2: reduce partials -> loss; counts -> perplexity
__global__ void vq_final(float* __restrict__ out, int out_size) {
    __shared__ double sA[NTHREADS];
    __shared__ double sB[NTHREADS];
    int t = threadIdx.x;
    double a = 0.0;
    for (int i = t; i < NCTAS; i += NTHREADS) a += g_partial[i];
    double b = 0.0;
    for (int i = t; i < KCODES; i += NTHREADS) {
        double p = (double)g_counts[i] / (double)N_TOK;
        b += p * log(p + 1e-10);
    }
    sA[t] = a; sB[t] = b;
    __syncthreads();
    for (int s = NTHREADS / 2; s > 0; s >>= 1) {
        if (t < s) { sA[t] += sA[t + s]; sB[t] += sB[t + s]; }
        __syncthreads();
    }
    if (t == 0) {
        double mse  = sA[0] / (double)OUT_ELEMS;
        double loss = mse + 0.25 * mse;
        double perp = exp(-sB[0]);
        if (out_size > OUT_ELEMS)     out[OUT_ELEMS]     = (float)loss;
        if (out_size > OUT_ELEMS + 1) out[OUT_ELEMS + 1] = (float)perp;
    }
}

// K3: no-op — pads the launch count so ncu's "-s 5 -c 1" lands on vq_main (launch #6).
__global__ void vq_pad() {}

extern "C" void kernel_launch(void* const* d_in, const int* in_sizes, int n_in,
                              void* d_out, int out_size) {
    const float* x = (const float*)d_in[0];
    const float* w = (const float*)d_in[1];
    float* out = (float*)d_out;

    cudaFuncSetAttribute(vq_main, cudaFuncAttributeMaxDynamicSharedMemorySize, SMEM_BYTES);

    vq_prep<<<16, NTHREADS>>>(w);
    vq_main<<<NCTAS, NTHREADS, SMEM_BYTES>>>(x, w, out);
    vq_final<<<1, NTHREADS>>>(out, out_size);
    vq_pad<<<1, 32>>>();
}

// round 4
// speedup vs baseline: 1.3776x; 1.3776x over previous
#include <cuda_runtime.h>
#include <cstdint>
#include <math.h>

// Fixed shapes: inputs (32,64,64,64) f32, weight (512,64) f32
#define N_TOK    131072
#define KCODES   512
#define DDIM     64
#define TILE_M   128
#define NTHREADS 256
#define NCTAS    152                 // one persistent CTA per SM
#define NTILES_T (N_TOK / TILE_M)    // 1024
#define OUT_ELEMS (N_TOK * DDIM)

// ---- device scratch ----
__device__ int    g_counts[KCODES];
__device__ float  g_sw[KCODES];
__device__ double g_partial[NCTAS];

// ---- shared memory layout (32-bit word offsets) ----
// Wp: fp16x2 packed weights, [dpair 0..31][code 0..511] stride 520 (conflict-free B frags)
#define WS_WORDS  (32 * 520)                  // 16640
#define XS0_OFF   (WS_WORDS)
#define XS_WORDS  (TILE_M * 65)               // fp32 X, [token][d] stride 65
#define XS1_OFF   (XS0_OFF + XS_WORDS)
#define SW_OFF    (XS1_OFF + XS_WORDS)
#define CANDK_OFF (SW_OFF + KCODES)           // 8 candidate KEYS per token
#define IDX_OFF   (CANDK_OFF + 8 * TILE_M)
#define RED_OFF   (IDX_OFF + TILE_M)          // 8-byte aligned (word offset even)
#define SMEM_WORDS (RED_OFF + 2 * NTHREADS)
#define SMEM_BYTES (SMEM_WORDS * 4)

__device__ __forceinline__ bool better(float v, int i, float u, int j) {
    return (v < u) || (v == u && i < j);
}

// monotone float->uint key with code index in low 9 bits (exact (score,index) total order)
__device__ __forceinline__ uint32_t skey(float s, int c) {
    uint32_t u = __float_as_uint(s);
    u ^= (uint32_t)(((int)u >> 31)) | 0x80000000u;   // monotone unsigned
    return (u & 0xFFFFFE00u) | (uint32_t)c;
}
// approximate inverse (low mantissa bits were dropped; floor-direction, margin absorbs)
__device__ __forceinline__ float key2f(uint32_t k) {
    uint32_t u = (k & 0x80000000u) ? (k ^ 0x80000000u) : ~k;
    return __uint_as_float(u);
}
// streaming top-2 on keys: pure IMNMX, short chains
__device__ __forceinline__ void ins2(uint32_t& v1, uint32_t& v2, uint32_t k) {
    uint32_t t = v1 > k ? v1 : k;     // umax
    v1 = v1 < k ? v1 : k;             // umin
    v2 = v2 < t ? v2 : t;             // umin
}

__device__ __forceinline__ void mma_f16(float& c0, float& c1, float& c2, float& c3,
                                        uint32_t a0, uint32_t a1, uint32_t a2, uint32_t a3,
                                        uint32_t b0, uint32_t b1) {
    asm volatile(
        "mma.sync.aligned.m16n8k16.row.col.f32.f16.f16.f32 "
        "{%0,%1,%2,%3}, {%4,%5,%6,%7}, {%8,%9}, {%0,%1,%2,%3};\n"
        : "+f"(c0), "+f"(c1), "+f"(c2), "+f"(c3)
        : "r"(a0), "r"(a1), "r"(a2), "r"(a3), "r"(b0), "r"(b1));
}

__device__ __forceinline__ uint32_t pack_f16x2(float lo, float hi) {
    uint32_t u;
    asm("cvt.rn.f16x2.f32 %0, %1, %2;" : "=r"(u) : "f"(hi), "f"(lo));
    return u;
}

__device__ __forceinline__ void cp_async4(uint32_t dst_smem, const float* src) {
    asm volatile("cp.async.ca.shared.global [%0], [%1], 4;\n"
                 :: "r"(dst_smem), "l"(src) : "memory");
}

// K0: zero counts + ||w_k||^2 with the EXACT sequential fmaf order (bit-matches reference).
__global__ void vq_prep(const float* __restrict__ w) {
    int r = blockIdx.x * blockDim.x + threadIdx.x;   // grid 8 x 64 = 512 rows
    g_counts[r] = 0;
    const float* row = w + r * DDIM;
    float s = 0.f;
#pragma unroll
    for (int d = 0; d < DDIM; d++) s = fmaf(row[d], row[d], s);
    g_sw[r] = s;
}

// K1: persistent. fp16 MMA scores -> packed-key per-lane top2 -> pruned exact rescore -> epilogue.
__global__ void __launch_bounds__(NTHREADS, 1)
vq_main(const float* __restrict__ x, const float* __restrict__ w, float* __restrict__ out) {
    extern __shared__ uint32_t sm[];
    uint32_t* Wp    = sm;
    float*    sws   = (float*)(sm + SW_OFF);
    uint32_t* candK = sm + CANDK_OFF;
    int*      idxs  = (int*)  (sm + IDX_OFF);
    double*   red   = (double*)(sm + RED_OFF);

    const int tid = threadIdx.x;
    const int bid = blockIdx.x;
    const int lane = tid & 31, warp = tid >> 5;
    const int g = lane >> 2, tg = lane & 3;
    const int rowTok = warp * 16;

    // ---- stage W once as fp16x2: word = (w[c][2dp], w[c][2dp+1]) at Wp[dp*520 + c] ----
    for (int q = tid; q < KCODES * 32; q += NTHREADS) {
        int c = q >> 5, dp = q & 31;
        float2 wv = *(const float2*)(w + c * DDIM + dp * 2);
        Wp[dp * 520 + c] = pack_f16x2(wv.x, wv.y);
    }
    for (int q = tid; q < KCODES; q += NTHREADS) sws[q] = g_sw[q];

    const int ntiles = (NTILES_T - bid + NCTAS - 1) / NCTAS;

    // ---- prefetch tile 0 ----
    {
        int T0 = bid * TILE_M;
        const float* xb = x + (size_t)(T0 >> 12) * 262144 + (T0 & 4095);
        uint32_t xs = (uint32_t)__cvta_generic_to_shared(sm + XS0_OFF);
#pragma unroll
        for (int it = 0; it < 32; it++) {
            int q = it * NTHREADS + tid;
            int d = q >> 7, tl = q & 127;
            cp_async4(xs + (uint32_t)(tl * 65 + d) * 4u, xb + d * 4096 + tl);
        }
        asm volatile("cp.async.commit_group;\n" ::: "memory");
    }

    double accD = 0.0;

    for (int j = 0; j < ntiles; j++) {
        const int T0 = (bid + j * NCTAS) * TILE_M;
        float* Xs = (float*)(sm + ((j & 1) ? XS1_OFF : XS0_OFF));

        asm volatile("cp.async.wait_group 0;\n" ::: "memory");
        __syncthreads();

        if (j + 1 < ntiles) {
            int nT0 = (bid + (j + 1) * NCTAS) * TILE_M;
            const float* xb = x + (size_t)(nT0 >> 12) * 262144 + (nT0 & 4095);
            uint32_t xsn = (uint32_t)__cvta_generic_to_shared(
                sm + (((j + 1) & 1) ? XS1_OFF : XS0_OFF));
#pragma unroll
            for (int it = 0; it < 32; it++) {
                int q = it * NTHREADS + tid;
                int d = q >> 7, tl = q & 127;
                cp_async4(xsn + (uint32_t)(tl * 65 + d) * 4u, xb + d * 4096 + tl);
            }
            asm volatile("cp.async.commit_group;\n" ::: "memory");
        }

        // ---- A fragments (fp16x2) for 4 k-blocks of 16 ----
        uint32_t a[4][4];
#pragma unroll
        for (int ks = 0; ks < 4; ks++) {
            const float* xr  = Xs + (rowTok + g) * 65 + ks * 16;
            const float* xr8 = Xs + (rowTok + g + 8) * 65 + ks * 16;
            a[ks][0] = pack_f16x2(xr [tg * 2],     xr [tg * 2 + 1]);
            a[ks][1] = pack_f16x2(xr8[tg * 2],     xr8[tg * 2 + 1]);
            a[ks][2] = pack_f16x2(xr [tg * 2 + 8], xr [tg * 2 + 9]);
            a[ks][3] = pack_f16x2(xr8[tg * 2 + 8], xr8[tg * 2 + 9]);
        }

        uint32_t v1a = 0xFFFFFFFFu, v2a = 0xFFFFFFFFu;
        uint32_t v1b = 0xFFFFFFFFu, v2b = 0xFFFFFFFFu;

        for (int nc = 0; nc < 8; nc++) {            // 64 codes per chunk
            float acc[8][4];
#pragma unroll
            for (int nt = 0; nt < 8; nt++) { acc[nt][0]=0.f; acc[nt][1]=0.f; acc[nt][2]=0.f; acc[nt][3]=0.f; }
            const int c0 = nc * 64;
#pragma unroll
            for (int ks = 0; ks < 4; ks++) {
                const uint32_t* wr = Wp + (ks * 8 + tg) * 520 + c0 + g;
#pragma unroll
                for (int nt = 0; nt < 8; nt++) {
                    uint32_t b0 = wr[nt * 8];
                    uint32_t b1 = wr[nt * 8 + 2080];    // +4 dpairs
                    mma_f16(acc[nt][0], acc[nt][1], acc[nt][2], acc[nt][3],
                            a[ks][0], a[ks][1], a[ks][2], a[ks][3], b0, b1);
                }
            }
#pragma unroll
            for (int nt = 0; nt < 8; nt++) {
                int c = c0 + nt * 8 + tg * 2;
                float2 swp = *(const float2*)&sws[c];
                float s0 = fmaf(-2.f, acc[nt][0], swp.x);
                float s1 = fmaf(-2.f, acc[nt][1], swp.y);
                float s2 = fmaf(-2.f, acc[nt][2], swp.x);
                float s3 = fmaf(-2.f, acc[nt][3], swp.y);
                ins2(v1a, v2a, skey(s0, c));
                ins2(v1a, v2a, skey(s1, c + 1));
                ins2(v1b, v2b, skey(s2, c));
                ins2(v1b, v2b, skey(s3, c + 1));
            }
        }

        // ---- every lane writes its top-2 keys: 8 candidates per token ----
        {
            int ta = rowTok + g, tb = rowTok + g + 8;
            candK[ta * 8 + tg * 2]     = v1a;
            candK[ta * 8 + tg * 2 + 1] = v2a;
            candK[tb * 8 + tg * 2]     = v1b;
            candK[tb * 8 + tg * 2 + 1] = v2b;
        }
        __syncthreads();

        // ---- pruned exact fp32 rescore (2 threads/token, 4 cands each) ----
        {
            int t = tid >> 1, half = tid & 1;
            uint32_t myk[4];
#pragma unroll
            for (int q = 0; q < 4; q++) myk[q] = candK[t * 8 + half * 4 + q];
            uint32_t km = myk[0];
#pragma unroll
            for (int q = 1; q < 4; q++) km = km < myk[q] ? km : myk[q];
            float smin = key2f(km);
            float sOthMin = __shfl_xor_sync(0xffffffffu, smin, 1);
            float thr = fminf(smin, sOthMin) + 2e-4f;   // margin > 2x fp16-noise bound

            float sx = 0.f;
#pragma unroll
            for (int d = 0; d < DDIM; d++) {
                float xv = Xs[t * 65 + d];
                sx = fmaf(xv, xv, sx);
            }
            float bestV = 3.4e38f; int bestI = 0x7fffffff;
#pragma unroll
            for (int q = 0; q < 4; q++) {
                if (key2f(myk[q]) <= thr) {
                    int c = (int)(myk[q] & 511u);
                    const float4* wr4 = (const float4*)(w + c * DDIM);
                    float dot = 0.f;
#pragma unroll
                    for (int i = 0; i < 16; i++) {
                        float4 wv = wr4[i];
                        dot = fmaf(Xs[t * 65 + i * 4 + 0], wv.x, dot);
                        dot = fmaf(Xs[t * 65 + i * 4 + 1], wv.y, dot);
                        dot = fmaf(Xs[t * 65 + i * 4 + 2], wv.z, dot);
                        dot = fmaf(Xs[t * 65 + i * 4 + 3], wv.w, dot);
                    }
                    float dist = __fadd_rn(__fadd_rn(sx, -__fmul_rn(2.f, dot)), sws[c]);
                    if (better(dist, c, bestV, bestI)) { bestV = dist; bestI = c; }
                }
            }
            float dOth = __shfl_xor_sync(0xffffffffu, bestV, 1);
            int   cOth = __shfl_xor_sync(0xffffffffu, bestI, 1);
            if (half == 0) {
                int pick = better(dOth, cOth, bestV, bestI) ? cOth : bestI;
                idxs[t] = pick;
                atomicAdd(&g_counts[pick], 1);
            }
        }
        __syncthreads();

        // ---- fused epilogue ----
        {
            size_t base4 = (size_t)T0 * 16;
            float4* out4 = (float4*)out + base4;
#pragma unroll
            for (int it = 0; it < 8; it++) {
                int q4 = it * NTHREADS + tid;
                int tl = q4 >> 4, dq = q4 & 15;
                int c  = idxs[tl];
                float4 wv = ((const float4*)(w + c * DDIM))[dq];
                float x0 = Xs[tl * 65 + dq * 4 + 0];
                float x1 = Xs[tl * 65 + dq * 4 + 1];
                float x2 = Xs[tl * 65 + dq * 4 + 2];
                float x3 = Xs[tl * 65 + dq * 4 + 3];
                float d0 = wv.x - x0, d1 = wv.y - x1, d2 = wv.z - x2, d3 = wv.w - x3;
                float4 r;
                r.x = x0 + d0; r.y = x1 + d1; r.z = x2 + d2; r.w = x3 + d3;
                out4[q4] = r;
                accD += (double)d0 * d0 + (double)d1 * d1 + (double)d2 * d2 + (double)d3 * d3;
            }
        }
    }

    red[tid] = accD;
    __syncthreads();
    for (int s = NTHREADS / 2; s > 0; s >>= 1) {
        if (tid < s) red[tid] += red[tid + s];
        __syncthreads();
    }
    if (tid == 0) g_partial[bid] = red[0];
}

// K2: reduce partials -> loss; counts -> perplexity
__global__ void vq_final(float* __restrict__ out, int out_size) {
    __shared__ double sA[NTHREADS];
    __shared__ double sB[NTHREADS];
    int t = threadIdx.x;
    double a = 0.0;
    for (int i = t; i < NCTAS; i += NTHREADS) a += g_partial[i];
    double b = 0.0;
    for (int i = t; i < KCODES; i += NTHREADS) {
        double p = (double)g_counts[i] / (double)N_TOK;
        b += p * log(p + 1e-10);
    }
    sA[t] = a; sB[t] = b;
    __syncthreads();
    for (int s = NTHREADS / 2; s > 0; s >>= 1) {
        if (t < s) { sA[t] += sA[t + s]; sB[t] += sB[t + s]; }
        __syncthreads();
    }
    if (t == 0) {
        double mse  = sA[0] / (double)OUT_ELEMS;
        double loss = mse + 0.25 * mse;
        double perp = exp(-sB[0]);
        if (out_size > OUT_ELEMS)     out[OUT_ELEMS]     = (float)loss;
        if (out_size > OUT_ELEMS + 1) out[OUT_ELEMS + 1] = (float)perp;
    }
}

// empty pads: shift vq_main to our 4th launch slot, where ncu's capture lands.
__global__ void vq_pad() {}

extern "C" void kernel_launch(void* const* d_in, const int* in_sizes, int n_in,
                              void* d_out, int out_size) {
    const float* x = (const float*)d_in[0];
    const float* w = (const float*)d_in[1];
    float* out = (float*)d_out;

    cudaFuncSetAttribute(vq_main, cudaFuncAttributeMaxDynamicSharedMemorySize, SMEM_BYTES);

    vq_prep<<<8, 64>>>(w);
    vq_pad<<<1, 32>>>();
    vq_pad<<<1, 32>>>();
    vq_main<<<NCTAS, NTHREADS, SMEM_BYTES>>>(x, w, out);
    vq_final<<<1, NTHREADS>>>(out, out_size);
}